// round 16
// baseline (speedup 1.0000x reference)
#include <cuda_runtime.h>

// Problem constants
#define BB   32
#define NN   2048
#define DD   65
#define HH   64
#define DSQ  (DD*DD)        // 4225
#define GCH  64             // gram chunk rows per block
#define NGC  (NN/GCH)       // 32 partials per batch
#define OCH  128            // out chunk rows
#define NOC  (NN/OCH)       // 16
#define OP   72             // padded dim for tensor k_out (9 tiles of 8)

typedef unsigned long long ull;

// Scratch (no allocations allowed)
__device__ float g_Gpart[BB * NGC * DSQ];   // partial Gram matrices (~17.3 MB)
__device__ float g_G[BB * DSQ];             // reduced Gram
__device__ float g_M[BB * DSQ];             // M = A * G * Wv^T per batch

// ---- packed fp32x2 helpers ----
__device__ __forceinline__ ull pack2(float x) {
    ull d; unsigned u = __float_as_uint(x);
    asm("mov.b64 %0, {%1, %1};" : "=l"(d) : "r"(u));
    return d;
}
__device__ __forceinline__ ull fma2(ull a, ull b, ull c) {
    ull d;
    asm("fma.rn.f32x2 %0, %1, %2, %3;" : "=l"(d) : "l"(a), "l"(b), "l"(c));
    return d;
}
__device__ __forceinline__ void unpack2(ull d, float& lo, float& hi) {
    unsigned a, b;
    asm("mov.b64 {%0, %1}, %2;" : "=r"(a), "=r"(b) : "l"(d));
    lo = __uint_as_float(a); hi = __uint_as_float(b);
}
__device__ __forceinline__ void unpack2u(ull d, unsigned& lo, unsigned& hi) {
    asm("mov.b64 {%0, %1}, %2;" : "=r"(lo), "=r"(hi) : "l"(d));
}

// ---- tf32 helpers ----
__device__ __forceinline__ unsigned f2tf32(float v) {
    unsigned r; asm("cvt.rna.tf32.f32 %0, %1;" : "=r"(r) : "f"(v)); return r;
}
__device__ __forceinline__ void mma_tf32(float* d, const unsigned* a,
                                         unsigned b0, unsigned b1) {
    asm volatile(
        "mma.sync.aligned.m16n8k8.row.col.f32.tf32.tf32.f32 "
        "{%0,%1,%2,%3}, {%4,%5,%6,%7}, {%8,%9}, {%0,%1,%2,%3};"
        : "+f"(d[0]), "+f"(d[1]), "+f"(d[2]), "+f"(d[3])
        : "r"(a[0]), "r"(a[1]), "r"(a[2]), "r"(a[3]), "r"(b0), "r"(b1));
}

// ---------------------------------------------------------------------------
// Kernel 1 (proven): partial Gram, 64-row chunk, FFMA2 dup-buffer.
// grid (32, 32), block 256, dynamic smem 58368 B.
// ---------------------------------------------------------------------------
__global__ void __launch_bounds__(256) k_gram(const float* __restrict__ x) {
    extern __shared__ __align__(16) float smg[];
    float* xs   = smg;               // 64*68
    float* xdup = smg + GCH * 68;    // 64*160

    const int b = blockIdx.y, c = blockIdx.x;
    const int tid = threadIdx.x;
    const float* xp = x + ((size_t)b * NN + (size_t)c * GCH) * DD;

    for (int idx = tid; idx < GCH * DD; idx += 256) {
        int r = idx / DD, col = idx - r * DD;
        float v = xp[idx];
        xs[r * 68 + col] = v;
        xdup[r * 160 + 2 * col]     = v;
        xdup[r * 160 + 2 * col + 1] = v;
    }
    __syncthreads();

    const int ty = tid >> 4, tx = tid & 15;
    const int p0 = tx, p1 = 16 + tx, p2 = (tx == 0) ? 32 : 33;

    ull acc[5][3];
#pragma unroll
    for (int u = 0; u < 5; ++u)
#pragma unroll
        for (int v = 0; v < 3; ++v) acc[u][v] = 0ull;

#pragma unroll 4
    for (int k = 0; k < GCH; ++k) {
        const ull* xd = (const ull*)(xs + k * 68);
        const ull* ar = (const ull*)(xdup + k * 160);
        ull b0 = xd[p0], b1 = xd[p1], b2 = xd[p2];
#pragma unroll
        for (int u = 0; u < 5; ++u) {
            ull ad = ar[ty + 16 * u];
            acc[u][0] = fma2(ad, b0, acc[u][0]);
            acc[u][1] = fma2(ad, b1, acc[u][1]);
            acc[u][2] = fma2(ad, b2, acc[u][2]);
        }
    }

    float* gp = g_Gpart + (size_t)(b * NGC + c) * DSQ;
    const int pv[3] = {p0, p1, p2};
#pragma unroll
    for (int u = 0; u < 5; ++u) {
        int i = ty + 16 * u;
        if (i >= DD) continue;
#pragma unroll
        for (int v = 0; v < 3; ++v) {
            int j0 = 2 * pv[v];
            float lo, hi;
            unpack2(acc[u][v], lo, hi);
            if (j0     < DD) gp[i * DD + j0]     = lo;
            if (j0 + 1 < DD) gp[i * DD + j0 + 1] = hi;
        }
    }
}

// ---------------------------------------------------------------------------
// Kernel 2: reduce 32 partial Grams -> g_G.  grid (17, 32). (proven)
// ---------------------------------------------------------------------------
__global__ void k_reduce() {
    const int b = blockIdx.y;
    int idx = blockIdx.x * 256 + threadIdx.x;
    if (idx >= DSQ) return;
    const float* gp = g_Gpart + (size_t)b * NGC * DSQ + idx;
    float s0 = 0.f, s1 = 0.f, s2 = 0.f, s3 = 0.f;
#pragma unroll
    for (int c = 0; c < NGC; c += 4) {
        s0 += gp[(c + 0) * DSQ];
        s1 += gp[(c + 1) * DSQ];
        s2 += gp[(c + 2) * DSQ];
        s3 += gp[(c + 3) * DSQ];
    }
    g_G[b * DSQ + idx] = (s0 + s1) + (s2 + s3);
}

// ---------------------------------------------------------------------------
// Kernel 3 (proven): mid chain, tiled 3 ways per batch. grid (3, 32).
// ---------------------------------------------------------------------------
__global__ void __launch_bounds__(256) k_mid3(const float* __restrict__ Wq,
                                              const float* __restrict__ Wk,
                                              const float* __restrict__ Wv) {
    __shared__ __align__(16) float B1[DD * 68];
    __shared__ __align__(16) float B2[DD * 68];
    __shared__ __align__(16) float B3[32 * 68];

    const int b = blockIdx.y, t = blockIdx.x;
    const int tid = threadIdx.x;
    const int ty = tid >> 4, tx = tid & 15;
    const int p0 = tx, p1 = 16 + tx, p2 = (tx == 0) ? 32 : 33;
    const int pv[3] = {p0, p1, p2};
    const int i0 = t * 32;

    int iv[2];
#pragma unroll
    for (int u = 0; u < 2; ++u) {
        int i = i0 + ty + 16 * u;
        iv[u] = (i < DD) ? i : (DD - 1);
    }

    for (int idx = tid; idx < HH * DD; idx += 256) {
        int h = idx / DD, i = idx - h * DD;
        B1[h * 68 + i] = Wq[idx];
        B2[h * 68 + i] = Wk[idx];
    }
    __syncthreads();

    // phase 0: A-tile
    {
        ull acc[2][3];
#pragma unroll
        for (int u = 0; u < 2; ++u)
#pragma unroll
            for (int v = 0; v < 3; ++v) acc[u][v] = 0ull;
#pragma unroll 8
        for (int h = 0; h < HH; ++h) {
            const ull* kr = (const ull*)(B2 + h * 68);
            ull b0 = kr[p0], b1 = kr[p1], b2 = kr[p2];
            const float* qr = B1 + h * 68;
#pragma unroll
            for (int u = 0; u < 2; ++u) {
                ull ad = pack2(qr[iv[u]]);
                acc[u][0] = fma2(ad, b0, acc[u][0]);
                acc[u][1] = fma2(ad, b1, acc[u][1]);
                acc[u][2] = fma2(ad, b2, acc[u][2]);
            }
        }
        __syncthreads();
#pragma unroll
        for (int u = 0; u < 2; ++u) {
            ull* ap = (ull*)(B3 + (ty + 16 * u) * 68);
#pragma unroll
            for (int v = 0; v < 3; ++v) ap[pv[v]] = acc[u][v];
        }
    }
    for (int idx = tid; idx < DSQ; idx += 256) {
        int k = idx / DD, j = idx - k * DD;
        B2[k * 68 + j] = g_G[(size_t)b * DSQ + idx];
    }
    __syncthreads();

    // phase 1: T-tile = A-tile * G
    ull accT[2][3];
#pragma unroll
    for (int u = 0; u < 2; ++u)
#pragma unroll
        for (int v = 0; v < 3; ++v) accT[u][v] = 0ull;
#pragma unroll 5
    for (int k = 0; k < DD; ++k) {
        const ull* gr = (const ull*)(B2 + k * 68);
        ull b0 = gr[p0], b1 = gr[p1], b2 = gr[p2];
#pragma unroll
        for (int u = 0; u < 2; ++u) {
            ull ad = pack2(B3[(ty + 16 * u) * 68 + k]);
            accT[u][0] = fma2(ad, b0, accT[u][0]);
            accT[u][1] = fma2(ad, b1, accT[u][1]);
            accT[u][2] = fma2(ad, b2, accT[u][2]);
        }
    }
    __syncthreads();

#pragma unroll
    for (int u = 0; u < 2; ++u) {
        ull* tp = (ull*)(B3 + (ty + 16 * u) * 68);
#pragma unroll
        for (int v = 0; v < 3; ++v) tp[pv[v]] = accT[u][v];
    }
    for (int idx = tid; idx < DSQ; idx += 256) {
        int j = idx / DD, k = idx - j * DD;
        B1[k * 68 + j] = Wv[idx];
    }
    __syncthreads();

    // phase 2: M-tile = T-tile * Wv^T
    {
        ull acc[2][3];
#pragma unroll
        for (int u = 0; u < 2; ++u)
#pragma unroll
            for (int v = 0; v < 3; ++v) acc[u][v] = 0ull;
#pragma unroll 5
        for (int k = 0; k < DD; ++k) {
            const ull* wr = (const ull*)(B1 + k * 68);
            ull b0 = wr[p0], b1 = wr[p1], b2 = wr[p2];
#pragma unroll
            for (int u = 0; u < 2; ++u) {
                ull ad = pack2(B3[(ty + 16 * u) * 68 + k]);
                acc[u][0] = fma2(ad, b0, acc[u][0]);
                acc[u][1] = fma2(ad, b1, acc[u][1]);
                acc[u][2] = fma2(ad, b2, acc[u][2]);
            }
        }
        float* Mb = g_M + (size_t)b * DSQ;
#pragma unroll
        for (int u = 0; u < 2; ++u) {
            int i = i0 + ty + 16 * u;
            if (i >= DD) continue;
#pragma unroll
            for (int v = 0; v < 3; ++v) {
                int j0 = 2 * pv[v];
                float lo, hi;
                unpack2(acc[u][v], lo, hi);
                if (j0     < DD) Mb[i * DD + j0]     = lo;
                if (j0 + 1 < DD) Mb[i * DD + j0 + 1] = hi;
            }
        }
    }
}

// ---------------------------------------------------------------------------
// Kernel 4 (tensor core v3): out = x * M via tf32 mma.sync, 3-term split.
// grid (16, 32), block 256 (8 warps), OCH=128.
// CHANGE vs v2: Mhi/Mlo INTERLEAVED into one pair buffer Mhl[k][2j]={hi,lo}
// -> each B fragment is 2x LDS.64 instead of 4x LDS.32 (162 vs 324 B-loads
// per warp). Same smem footprint (41.5 KB). osm aliases Mhl after mainloop.
// ---------------------------------------------------------------------------
__global__ void __launch_bounds__(256, 3) k_out(const float* __restrict__ x,
                                                float* __restrict__ out) {
    extern __shared__ __align__(16) float smo[];
    float* Mhl = smo;                 // 72 rows x 144 floats (hi,lo pairs)
    float* osm = smo;                 // alias: reused after mainloop (128*65 <= 72*144)

    const int b = blockIdx.y, c = blockIdx.x;
    const float* xp = x + ((size_t)b * NN + (size_t)c * OCH) * DD;
    float* op = out + ((size_t)b * NN + (size_t)c * OCH) * DD;
    const int tid = threadIdx.x;

    // zero pads (whole buffer), then stage pre-split interleaved M
    for (int idx = tid; idx < OP * OP * 2; idx += 256)
        Mhl[idx] = 0.f;
    __syncthreads();
    const float* Mg = g_M + (size_t)b * DSQ;
    for (int idx = tid; idx < DSQ; idx += 256) {
        int k = idx / DD, j = idx - k * DD;
        float v = Mg[idx];
        unsigned hi = f2tf32(v);
        unsigned lo = f2tf32(v - __uint_as_float(hi));
        ((ull*)(Mhl + k * 144))[j] = (ull)hi | ((ull)lo << 32);
    }
    __syncthreads();

    const int warp = tid >> 5, lane = tid & 31;
    const int grp = lane >> 2, tig = lane & 3;
    const int m0 = warp * 16;
    const float* xr0 = xp + (m0 + grp) * DD;       // row m0+grp
    const float* xr8 = xp + (m0 + grp + 8) * DD;   // row m0+grp+8

    float acc[9][4];
#pragma unroll
    for (int nt = 0; nt < 9; ++nt)
#pragma unroll
        for (int q = 0; q < 4; ++q) acc[nt][q] = 0.f;

#pragma unroll
    for (int kt = 0; kt < 9; ++kt) {
        const int ka = kt * 8 + tig;       // <= 67
        const int kb = ka + 4;             // <= 71
        // A fragment from GLOBAL, predicated (pads = 0)
        float av[4];
        av[0] = (ka < DD) ? __ldg(xr0 + ka) : 0.f;
        av[1] = (ka < DD) ? __ldg(xr8 + ka) : 0.f;
        av[2] = (kb < DD) ? __ldg(xr0 + kb) : 0.f;
        av[3] = (kb < DD) ? __ldg(xr8 + kb) : 0.f;
        unsigned ahi[4], alo[4];
#pragma unroll
        for (int q = 0; q < 4; ++q) {
            ahi[q] = f2tf32(av[q]);
            alo[q] = f2tf32(av[q] - __uint_as_float(ahi[q]));
        }
        const ull* mr0 = (const ull*)(Mhl + (kt * 8 + tig)     * 144);
        const ull* mr1 = (const ull*)(Mhl + (kt * 8 + tig + 4) * 144);
#pragma unroll
        for (int nt = 0; nt < 9; ++nt) {
            const int n0 = nt * 8;
            unsigned bh0, bl0, bh1, bl1;
            unpack2u(mr0[n0 + grp], bh0, bl0);
            unpack2u(mr1[n0 + grp], bh1, bl1);
            mma_tf32(acc[nt], ahi, bh0, bh1);
            mma_tf32(acc[nt], ahi, bl0, bl1);
            mma_tf32(acc[nt], alo, bh0, bh1);
        }
    }

    __syncthreads();   // all Mhl reads done; reuse as output staging

#pragma unroll
    for (int nt = 0; nt < 9; ++nt) {
        const int n0 = nt * 8;
        int col0 = n0 + 2 * tig;
        int r0 = m0 + grp;
        if (col0 < DD) {
            osm[r0 * DD + col0]       = acc[nt][0];
            osm[(r0 + 8) * DD + col0] = acc[nt][2];
        }
        if (col0 + 1 < DD) {
            osm[r0 * DD + col0 + 1]       = acc[nt][1];
            osm[(r0 + 8) * DD + col0 + 1] = acc[nt][3];
        }
    }
    __syncthreads();

    for (int idx = tid; idx < OCH * DD; idx += 256)
        op[idx] = osm[idx];
}

// ---------------------------------------------------------------------------
extern "C" void kernel_launch(void* const* d_in, const int* in_sizes, int n_in,
                              void* d_out, int out_size) {
    const float* x  = (const float*)d_in[0];   // [32, 2048, 65]
    const float* Wq = (const float*)d_in[1];   // [64, 65]
    const float* Wk = (const float*)d_in[2];   // [64, 65]
    const float* Wv = (const float*)d_in[3];   // [65, 65]
    float* out = (float*)d_out;                // [32, 2048, 65]

    const int smem_gram = (GCH * 68 + GCH * 160) * 4;   // 58368 B
    const int smem_out  = (2 * OP * OP) * 4;            // 41472 B
    cudaFuncSetAttribute(k_gram, cudaFuncAttributeMaxDynamicSharedMemorySize, smem_gram);
    cudaFuncSetAttribute(k_out,  cudaFuncAttributeMaxDynamicSharedMemorySize, smem_out);

    k_gram<<<dim3(NGC, BB), 256, smem_gram>>>(x);
    k_reduce<<<dim3(17, BB), 256>>>();
    k_mid3<<<dim3(3, BB), 256>>>(Wq, Wk, Wv);
    k_out<<<dim3(NOC, BB), 256, smem_out>>>(x, out);
}

// round 17
// speedup vs baseline: 1.0146x; 1.0146x over previous
#include <cuda_runtime.h>

// Problem constants
#define BB   32
#define NN   2048
#define DD   65
#define HH   64
#define DSQ  (DD*DD)        // 4225
#define GCH  64             // gram chunk rows per block
#define NGC  (NN/GCH)       // 32 partials per batch
#define OCH  128            // out chunk rows
#define NOC  (NN/OCH)       // 16
#define OP   72             // padded dim for tensor k_out (9 tiles of 8)

typedef unsigned long long ull;

// Scratch (no allocations allowed)
__device__ float g_Gpart[BB * NGC * DSQ];   // partial Gram matrices (~17.3 MB)
__device__ float g_G[BB * DSQ];             // reduced Gram
__device__ float g_M[BB * DSQ];             // M = A * G * Wv^T per batch

// ---- packed fp32x2 helpers ----
__device__ __forceinline__ ull pack2(float x) {
    ull d; unsigned u = __float_as_uint(x);
    asm("mov.b64 %0, {%1, %1};" : "=l"(d) : "r"(u));
    return d;
}
__device__ __forceinline__ ull fma2(ull a, ull b, ull c) {
    ull d;
    asm("fma.rn.f32x2 %0, %1, %2, %3;" : "=l"(d) : "l"(a), "l"(b), "l"(c));
    return d;
}
__device__ __forceinline__ void unpack2(ull d, float& lo, float& hi) {
    unsigned a, b;
    asm("mov.b64 {%0, %1}, %2;" : "=r"(a), "=r"(b) : "l"(d));
    lo = __uint_as_float(a); hi = __uint_as_float(b);
}

// ---- tf32 helpers ----
__device__ __forceinline__ unsigned f2tf32(float v) {
    unsigned r; asm("cvt.rna.tf32.f32 %0, %1;" : "=r"(r) : "f"(v)); return r;
}
__device__ __forceinline__ void mma_tf32(float* d, const unsigned* a,
                                         unsigned b0, unsigned b1) {
    asm volatile(
        "mma.sync.aligned.m16n8k8.row.col.f32.tf32.tf32.f32 "
        "{%0,%1,%2,%3}, {%4,%5,%6,%7}, {%8,%9}, {%0,%1,%2,%3};"
        : "+f"(d[0]), "+f"(d[1]), "+f"(d[2]), "+f"(d[3])
        : "r"(a[0]), "r"(a[1]), "r"(a[2]), "r"(a[3]), "r"(b0), "r"(b1));
}

// ---------------------------------------------------------------------------
// Kernel 1: partial Gram with SYMMETRY SKIP. Computes only tiles that touch
// the upper triangle (i <= j) plus diagonal-crossing tiles:
//   skipped tiles (all-lane i>j): (u>=2, v=0) and (u=4, v=1)
// Inner loop: 11 fma2 per k (was 15). Mirror reconstructed in k_reduce.
// grid (32, 32), block 256, dynamic smem 58368 B.
// ---------------------------------------------------------------------------
__global__ void __launch_bounds__(256) k_gram(const float* __restrict__ x) {
    extern __shared__ __align__(16) float smg[];
    float* xs   = smg;               // 64*68  (b-side natural pairs)
    float* xdup = smg + GCH * 68;    // 64*160 (a-side duplicated pairs)

    const int b = blockIdx.y, c = blockIdx.x;
    const int tid = threadIdx.x;
    const float* xp = x + ((size_t)b * NN + (size_t)c * GCH) * DD;

    for (int idx = tid; idx < GCH * DD; idx += 256) {
        int r = idx / DD, col = idx - r * DD;
        float v = xp[idx];
        xs[r * 68 + col] = v;
        xdup[r * 160 + 2 * col]     = v;
        xdup[r * 160 + 2 * col + 1] = v;
    }
    __syncthreads();

    const int ty = tid >> 4, tx = tid & 15;
    const int p0 = tx, p1 = 16 + tx, p2 = (tx == 0) ? 32 : 33;  // pair 33 = pad (guarded)

    // kept accumulators: v=0 -> u<2; v=1 -> u<4; v=2 -> u<5
    ull a0[2], a1[4], a2[5];
#pragma unroll
    for (int u = 0; u < 2; ++u) a0[u] = 0ull;
#pragma unroll
    for (int u = 0; u < 4; ++u) a1[u] = 0ull;
#pragma unroll
    for (int u = 0; u < 5; ++u) a2[u] = 0ull;

#pragma unroll 4
    for (int k = 0; k < GCH; ++k) {
        const ull* xd = (const ull*)(xs + k * 68);
        const ull* ar = (const ull*)(xdup + k * 160);
        ull b0 = xd[p0], b1 = xd[p1], b2 = xd[p2];
        ull ad0 = ar[ty];
        ull ad1 = ar[ty + 16];
        ull ad2 = ar[ty + 32];
        ull ad3 = ar[ty + 48];
        ull ad4 = ar[ty + 64];
        a0[0] = fma2(ad0, b0, a0[0]);
        a0[1] = fma2(ad1, b0, a0[1]);
        a1[0] = fma2(ad0, b1, a1[0]);
        a1[1] = fma2(ad1, b1, a1[1]);
        a1[2] = fma2(ad2, b1, a1[2]);
        a1[3] = fma2(ad3, b1, a1[3]);
        a2[0] = fma2(ad0, b2, a2[0]);
        a2[1] = fma2(ad1, b2, a2[1]);
        a2[2] = fma2(ad2, b2, a2[2]);
        a2[3] = fma2(ad3, b2, a2[3]);
        a2[4] = fma2(ad4, b2, a2[4]);
    }

    float* gp = g_Gpart + (size_t)(b * NGC + c) * DSQ;
    // v=0 stores (u<2): i = ty+16u < 32 always valid; j0 = 2*p0 <= 30
#pragma unroll
    for (int u = 0; u < 2; ++u) {
        int i = ty + 16 * u;
        float lo, hi;
        unpack2(a0[u], lo, hi);
        gp[i * DD + 2 * p0]     = lo;
        gp[i * DD + 2 * p0 + 1] = hi;
    }
    // v=1 stores (u<4): i < 64, j0 = 2*p1 in [32,62]
#pragma unroll
    for (int u = 0; u < 4; ++u) {
        int i = ty + 16 * u;
        float lo, hi;
        unpack2(a1[u], lo, hi);
        gp[i * DD + 2 * p1]     = lo;
        gp[i * DD + 2 * p1 + 1] = hi;
    }
    // v=2 stores (u<5): guards on both i and j
#pragma unroll
    for (int u = 0; u < 5; ++u) {
        int i = ty + 16 * u;
        if (i >= DD) continue;
        int j0 = 2 * p2;
        float lo, hi;
        unpack2(a2[u], lo, hi);
        if (j0     < DD) gp[i * DD + j0]     = lo;
        if (j0 + 1 < DD) gp[i * DD + j0 + 1] = hi;
    }
}

// ---------------------------------------------------------------------------
// Kernel 2: reduce 32 partial Grams -> g_G, reconstructing the mirrored
// (skipped) lower-triangle region from the transposed index.
// skipped(i,j) = (i>=32 && j<32) || (i==64 && 32<=j<64)
// grid (17, 32), block 256.
// ---------------------------------------------------------------------------
__global__ void k_reduce() {
    const int b = blockIdx.y;
    int idx = blockIdx.x * 256 + threadIdx.x;
    if (idx >= DSQ) return;
    int i = idx / DD, j = idx - i * DD;
    bool sk = (i >= 32 && j < 32) || (i == 64 && j >= 32 && j < 64);
    int src = sk ? (j * DD + i) : idx;
    const float* gp = g_Gpart + (size_t)b * NGC * DSQ + src;
    float s0 = 0.f, s1 = 0.f, s2 = 0.f, s3 = 0.f;
#pragma unroll
    for (int c = 0; c < NGC; c += 4) {
        s0 += gp[(c + 0) * DSQ];
        s1 += gp[(c + 1) * DSQ];
        s2 += gp[(c + 2) * DSQ];
        s3 += gp[(c + 3) * DSQ];
    }
    g_G[b * DSQ + idx] = (s0 + s1) + (s2 + s3);
}

// ---------------------------------------------------------------------------
// Kernel 3 (proven): mid chain, tiled 3 ways per batch. grid (3, 32).
// ---------------------------------------------------------------------------
__global__ void __launch_bounds__(256) k_mid3(const float* __restrict__ Wq,
                                              const float* __restrict__ Wk,
                                              const float* __restrict__ Wv) {
    __shared__ __align__(16) float B1[DD * 68];
    __shared__ __align__(16) float B2[DD * 68];
    __shared__ __align__(16) float B3[32 * 68];

    const int b = blockIdx.y, t = blockIdx.x;
    const int tid = threadIdx.x;
    const int ty = tid >> 4, tx = tid & 15;
    const int p0 = tx, p1 = 16 + tx, p2 = (tx == 0) ? 32 : 33;
    const int pv[3] = {p0, p1, p2};
    const int i0 = t * 32;

    int iv[2];
#pragma unroll
    for (int u = 0; u < 2; ++u) {
        int i = i0 + ty + 16 * u;
        iv[u] = (i < DD) ? i : (DD - 1);
    }

    for (int idx = tid; idx < HH * DD; idx += 256) {
        int h = idx / DD, i = idx - h * DD;
        B1[h * 68 + i] = Wq[idx];
        B2[h * 68 + i] = Wk[idx];
    }
    __syncthreads();

    // phase 0: A-tile
    {
        ull acc[2][3];
#pragma unroll
        for (int u = 0; u < 2; ++u)
#pragma unroll
            for (int v = 0; v < 3; ++v) acc[u][v] = 0ull;
#pragma unroll 8
        for (int h = 0; h < HH; ++h) {
            const ull* kr = (const ull*)(B2 + h * 68);
            ull b0 = kr[p0], b1 = kr[p1], b2 = kr[p2];
            const float* qr = B1 + h * 68;
#pragma unroll
            for (int u = 0; u < 2; ++u) {
                ull ad = pack2(qr[iv[u]]);
                acc[u][0] = fma2(ad, b0, acc[u][0]);
                acc[u][1] = fma2(ad, b1, acc[u][1]);
                acc[u][2] = fma2(ad, b2, acc[u][2]);
            }
        }
        __syncthreads();
#pragma unroll
        for (int u = 0; u < 2; ++u) {
            ull* ap = (ull*)(B3 + (ty + 16 * u) * 68);
#pragma unroll
            for (int v = 0; v < 3; ++v) ap[pv[v]] = acc[u][v];
        }
    }
    for (int idx = tid; idx < DSQ; idx += 256) {
        int k = idx / DD, j = idx - k * DD;
        B2[k * 68 + j] = g_G[(size_t)b * DSQ + idx];
    }
    __syncthreads();

    // phase 1: T-tile = A-tile * G
    ull accT[2][3];
#pragma unroll
    for (int u = 0; u < 2; ++u)
#pragma unroll
        for (int v = 0; v < 3; ++v) accT[u][v] = 0ull;
#pragma unroll 5
    for (int k = 0; k < DD; ++k) {
        const ull* gr = (const ull*)(B2 + k * 68);
        ull b0 = gr[p0], b1 = gr[p1], b2 = gr[p2];
#pragma unroll
        for (int u = 0; u < 2; ++u) {
            ull ad = pack2(B3[(ty + 16 * u) * 68 + k]);
            accT[u][0] = fma2(ad, b0, accT[u][0]);
            accT[u][1] = fma2(ad, b1, accT[u][1]);
            accT[u][2] = fma2(ad, b2, accT[u][2]);
        }
    }
    __syncthreads();

#pragma unroll
    for (int u = 0; u < 2; ++u) {
        ull* tp = (ull*)(B3 + (ty + 16 * u) * 68);
#pragma unroll
        for (int v = 0; v < 3; ++v) tp[pv[v]] = accT[u][v];
    }
    for (int idx = tid; idx < DSQ; idx += 256) {
        int j = idx / DD, k = idx - j * DD;
        B1[k * 68 + j] = Wv[idx];
    }
    __syncthreads();

    // phase 2: M-tile = T-tile * Wv^T
    {
        ull acc[2][3];
#pragma unroll
        for (int u = 0; u < 2; ++u)
#pragma unroll
            for (int v = 0; v < 3; ++v) acc[u][v] = 0ull;
#pragma unroll 5
        for (int k = 0; k < DD; ++k) {
            const ull* wr = (const ull*)(B1 + k * 68);
            ull b0 = wr[p0], b1 = wr[p1], b2 = wr[p2];
#pragma unroll
            for (int u = 0; u < 2; ++u) {
                ull ad = pack2(B3[(ty + 16 * u) * 68 + k]);
                acc[u][0] = fma2(ad, b0, acc[u][0]);
                acc[u][1] = fma2(ad, b1, acc[u][1]);
                acc[u][2] = fma2(ad, b2, acc[u][2]);
            }
        }
        float* Mb = g_M + (size_t)b * DSQ;
#pragma unroll
        for (int u = 0; u < 2; ++u) {
            int i = i0 + ty + 16 * u;
            if (i >= DD) continue;
#pragma unroll
            for (int v = 0; v < 3; ++v) {
                int j0 = 2 * pv[v];
                float lo, hi;
                unpack2(acc[u][v], lo, hi);
                if (j0     < DD) Mb[i * DD + j0]     = lo;
                if (j0 + 1 < DD) Mb[i * DD + j0 + 1] = hi;
            }
        }
    }
}

// ---------------------------------------------------------------------------
// Kernel 4 (R15 tensor core, proven 31.4us): out = x * M via tf32 mma.sync,
// 3-term split. grid (16, 32), block 256 (8 warps), OCH=128.
// A-fragments from global (predicated); smem = Mhi|Mlo (41.5 KB);
// epilogue osm aliases Mhi. __launch_bounds__(256,3).
// ---------------------------------------------------------------------------
__global__ void __launch_bounds__(256, 3) k_out(const float* __restrict__ x,
                                                float* __restrict__ out) {
    extern __shared__ __align__(16) float smo[];
    float* Mhi = smo;                 // 72*72
    float* Mlo = smo + OP * OP;       // 72*72
    float* osm = smo;                 // alias: reused after mainloop

    const int b = blockIdx.y, c = blockIdx.x;
    const float* xp = x + ((size_t)b * NN + (size_t)c * OCH) * DD;
    float* op = out + ((size_t)b * NN + (size_t)c * OCH) * DD;
    const int tid = threadIdx.x;

    for (int idx = tid; idx < OP * OP; idx += 256) {
        Mhi[idx] = 0.f;
        Mlo[idx] = 0.f;
    }
    __syncthreads();
    const float* Mg = g_M + (size_t)b * DSQ;
    for (int idx = tid; idx < DSQ; idx += 256) {
        int k = idx / DD, j = idx - k * DD;
        float v = Mg[idx];
        unsigned hi = f2tf32(v);
        float lof = v - __uint_as_float(hi);
        Mhi[k * OP + j] = __uint_as_float(hi);
        Mlo[k * OP + j] = __uint_as_float(f2tf32(lof));
    }
    __syncthreads();

    const int warp = tid >> 5, lane = tid & 31;
    const int grp = lane >> 2, tig = lane & 3;
    const int m0 = warp * 16;
    const float* xr0 = xp + (m0 + grp) * DD;
    const float* xr8 = xp + (m0 + grp + 8) * DD;

    float acc[9][4];
#pragma unroll
    for (int nt = 0; nt < 9; ++nt)
#pragma unroll
        for (int q = 0; q < 4; ++q) acc[nt][q] = 0.f;

#pragma unroll
    for (int kt = 0; kt < 9; ++kt) {
        const int ka = kt * 8 + tig;
        const int kb = ka + 4;
        float av[4];
        av[0] = (ka < DD) ? __ldg(xr0 + ka) : 0.f;
        av[1] = (ka < DD) ? __ldg(xr8 + ka) : 0.f;
        av[2] = (kb < DD) ? __ldg(xr0 + kb) : 0.f;
        av[3] = (kb < DD) ? __ldg(xr8 + kb) : 0.f;
        unsigned ahi[4], alo[4];
#pragma unroll
        for (int q = 0; q < 4; ++q) {
            ahi[q] = f2tf32(av[q]);
            alo[q] = f2tf32(av[q] - __uint_as_float(ahi[q]));
        }
        const int k0 = kt * 8;
#pragma unroll
        for (int nt = 0; nt < 9; ++nt) {
            const int n0 = nt * 8;
            unsigned bh0 = __float_as_uint(Mhi[(k0 + tig)     * OP + n0 + grp]);
            unsigned bh1 = __float_as_uint(Mhi[(k0 + tig + 4) * OP + n0 + grp]);
            unsigned bl0 = __float_as_uint(Mlo[(k0 + tig)     * OP + n0 + grp]);
            unsigned bl1 = __float_as_uint(Mlo[(k0 + tig + 4) * OP + n0 + grp]);
            mma_tf32(acc[nt], ahi, bh0, bh1);
            mma_tf32(acc[nt], ahi, bl0, bl1);
            mma_tf32(acc[nt], alo, bh0, bh1);
        }
    }

    __syncthreads();

#pragma unroll
    for (int nt = 0; nt < 9; ++nt) {
        const int n0 = nt * 8;
        int col0 = n0 + 2 * tig;
        int r0 = m0 + grp;
        if (col0 < DD) {
            osm[r0 * DD + col0]       = acc[nt][0];
            osm[(r0 + 8) * DD + col0] = acc[nt][2];
        }
        if (col0 + 1 < DD) {
            osm[r0 * DD + col0 + 1]       = acc[nt][1];
            osm[(r0 + 8) * DD + col0 + 1] = acc[nt][3];
        }
    }
    __syncthreads();

    for (int idx = tid; idx < OCH * DD; idx += 256)
        op[idx] = osm[idx];
}

// ---------------------------------------------------------------------------
extern "C" void kernel_launch(void* const* d_in, const int* in_sizes, int n_in,
                              void* d_out, int out_size) {
    const float* x  = (const float*)d_in[0];   // [32, 2048, 65]
    const float* Wq = (const float*)d_in[1];   // [64, 65]
    const float* Wk = (const float*)d_in[2];   // [64, 65]
    const float* Wv = (const float*)d_in[3];   // [65, 65]
    float* out = (float*)d_out;                // [32, 2048, 65]

    const int smem_gram = (GCH * 68 + GCH * 160) * 4;   // 58368 B
    const int smem_out  = (2 * OP * OP) * 4;            // 41472 B
    cudaFuncSetAttribute(k_gram, cudaFuncAttributeMaxDynamicSharedMemorySize, smem_gram);
    cudaFuncSetAttribute(k_out,  cudaFuncAttributeMaxDynamicSharedMemorySize, smem_out);

    k_gram<<<dim3(NGC, BB), 256, smem_gram>>>(x);
    k_reduce<<<dim3(17, BB), 256>>>();
    k_mid3<<<dim3(3, BB), 256>>>(Wq, Wk, Wv);
    k_out<<<dim3(NOC, BB), 256, smem_out>>>(x, out);
}